// round 17
// baseline (speedup 1.0000x reference)
#include <cuda_runtime.h>
#include <cuda_bf16.h>
#include <math.h>
#include <stdint.h>

// ---------------------------------------------------------------------------
// MLA forward. Projections: tf32x3 mma.m16n8k8 (measured 2x per-FLOP vs the
// bf16 m16n8k16 legacy pipe on sm_100: 586 vs 283 TF/s tensor). Attention:
// bf16x3 + ldmatrix (unchanged). Weight/x pre-splitting deleted.
// ---------------------------------------------------------------------------

#define ROWS 4096
#define TDIM 2048
#define CDIM 2048
#define HNUM 16
#define DH   128
#define HD2  64

// ------------------------- scratch (device globals) ------------------------
__device__ float g_kvd [ROWS * 512];
__device__ float g_qd  [ROWS * 512];
__device__ float g_vl  [ROWS * 2048];
__device__ float g_kr  [ROWS * 1024];
__device__ float g_qr  [ROWS * 1024];
__device__ float g_attn[ROWS * 2048];
__device__ uint32_t g_QH[ROWS * 1024], g_QM[ROWS * 1024];
__device__ uint32_t g_KH[ROWS * 1024], g_KM[ROWS * 1024];
__device__ uint32_t g_VTH[2 * HNUM * 128 * 1024], g_VTM[2 * HNUM * 128 * 1024];

// =========================== helpers =======================================
__device__ __forceinline__ uint32_t smem_u32(const void* p) {
    uint32_t a;
    asm("{ .reg .u64 t; cvta.to.shared.u64 t, %1; cvt.u32.u64 %0, t; }"
        : "=r"(a) : "l"(p));
    return a;
}
__device__ __forceinline__ void cp16(uint32_t dst, const void* src) {
    asm volatile("cp.async.cg.shared.global [%0], [%1], 16;"
                 :: "r"(dst), "l"(src));
}
#define CP_COMMIT() asm volatile("cp.async.commit_group;" ::: "memory")
#define CP_WAIT(n)  asm volatile("cp.async.wait_group %0;" :: "n"(n) : "memory")

__device__ __forceinline__ uint32_t tf32_hi(float x) {
    uint32_t u;
    asm("cvt.rna.tf32.f32 %0, %1;" : "=r"(u) : "f"(x));
    return u;
}
__device__ __forceinline__ void split32(float x, uint32_t& hi, uint32_t& lo) {
    hi = tf32_hi(x);
    lo = __float_as_uint(x - __uint_as_float(hi));
}
__device__ __forceinline__ void mma_tf32(float* d, const uint32_t* a,
                                         const uint32_t* b) {
    asm volatile(
        "mma.sync.aligned.m16n8k8.row.col.f32.tf32.tf32.f32 "
        "{%0,%1,%2,%3}, {%4,%5,%6,%7}, {%8,%9}, {%0,%1,%2,%3};"
        : "+f"(d[0]), "+f"(d[1]), "+f"(d[2]), "+f"(d[3])
        : "r"(a[0]), "r"(a[1]), "r"(a[2]), "r"(a[3]), "r"(b[0]), "r"(b[1]));
}
__device__ __forceinline__ void mma_bf16(float* d, const uint32_t* a,
                                         const uint32_t* b) {
    asm volatile(
        "mma.sync.aligned.m16n8k16.row.col.f32.bf16.bf16.f32 "
        "{%0,%1,%2,%3}, {%4,%5,%6,%7}, {%8,%9}, {%0,%1,%2,%3};"
        : "+f"(d[0]), "+f"(d[1]), "+f"(d[2]), "+f"(d[3])
        : "r"(a[0]), "r"(a[1]), "r"(a[2]), "r"(a[3]), "r"(b[0]), "r"(b[1]));
}
__device__ __forceinline__ void ldsm_x4(uint32_t& r0, uint32_t& r1,
                                        uint32_t& r2, uint32_t& r3,
                                        uint32_t addr) {
    asm volatile("ldmatrix.sync.aligned.m8n8.x4.shared.b16 {%0,%1,%2,%3}, [%4];"
                 : "=r"(r0), "=r"(r1), "=r"(r2), "=r"(r3) : "r"(addr));
}
__device__ __forceinline__ void split_pack(float x0, float x1,
                                           uint32_t& wh, uint32_t& wm) {
    __nv_bfloat162 hh = __floats2bfloat162_rn(x0, x1);
    float f0 = __low2float(hh), f1 = __high2float(hh);
    __nv_bfloat162 mm = __floats2bfloat162_rn(x0 - f0, x1 - f1);
    wh = reinterpret_cast<uint32_t&>(hh);
    wm = reinterpret_cast<uint32_t&>(mm);
}
__device__ __forceinline__ float fexp(float x) {
    float t  = x * 1.4426950408889634f;
    float kf = rintf(t);
    float y  = (t - kf) * 0.6931471805599453f;
    float r  = fmaf(y, 1.3888888889e-3f, 8.3333333333e-3f);
    r = fmaf(y, r, 4.1666666667e-2f);
    r = fmaf(y, r, 1.6666666667e-1f);
    r = fmaf(y, r, 0.5f);
    r = fmaf(y, r, 1.0f);
    r = fmaf(y, r, 1.0f);
    int ki = (int)fmaxf(kf, -127.0f);
    return r * __int_as_float((ki + 127) << 23);
}

// ====================== tf32x3 batch GEMM (R3 core) ========================
// C[M,N] = A[M,K]*B[N,K]^T, fp32 inputs. CTA 128x128, 8 warps (2x4),
// warp 64x32, K-step 32, 3-stage cp.async pipeline (R3: 586 TF/s tensor).
#define GPAD     36
#define GST_B    (128 * GPAD * 4)
#define GSTAGE_B (2 * GST_B)
#define GEMM_SMEM (3 * GSTAGE_B)      // 110592 B

#define OM_F32   0
#define OM_QKMAP 2

struct GSeg {
    const float *A, *B;
    float* cF; uint32_t *cH, *cM;
    int ldF, ldW, mode, end;
};
struct GBatch { GSeg s[4]; };

__global__ __launch_bounds__(256) void gemm_tf32(GBatch gb, int K)
{
    extern __shared__ __align__(16) float sm[];
    const uint32_t smb = smem_u32(sm);
    const int tid  = threadIdx.x;
    const int wid  = tid >> 5, lane = tid & 31;
    const int wm   = wid >> 2, wn = wid & 3;
    const int r    = lane >> 2, q = lane & 3;
    const int bm   = blockIdx.y * 128;

    GSeg sg; int bn;
    {
        int bx = blockIdx.x;
        if (bx < gb.s[0].end)      { sg = gb.s[0]; bn = bx * 128; }
        else if (bx < gb.s[1].end) { sg = gb.s[1]; bn = (bx - gb.s[0].end) * 128; }
        else if (bx < gb.s[2].end) { sg = gb.s[2]; bn = (bx - gb.s[1].end) * 128; }
        else                       { sg = gb.s[3]; bn = (bx - gb.s[2].end) * 128; }
    }

    float c[4][4][4];
#pragma unroll
    for (int i = 0; i < 4; i++)
#pragma unroll
        for (int j = 0; j < 4; j++)
#pragma unroll
            for (int e = 0; e < 4; e++) c[i][j][e] = 0.f;

    const int KT = K / 32;

    auto issue = [&](int s, int k0) {
#pragma unroll
        for (int j = 0; j < 4; j++) {
            int f = tid + j * 256;
            int row = f >> 3, c4 = f & 7;
            uint32_t off = (uint32_t)(s * GSTAGE_B + row * (GPAD * 4) + c4 * 16);
            cp16(smb + off, &sg.A[(size_t)(bm + row) * K + k0 + c4 * 4]);
            cp16(smb + off + GST_B, &sg.B[(size_t)(bn + row) * K + k0 + c4 * 4]);
        }
    };

    issue(0, 0);  CP_COMMIT();
    issue(1, 32); CP_COMMIT();

    for (int it = 0; it < KT; it++) {
        CP_WAIT(1);
        __syncthreads();

        if (it + 2 < KT) issue((it + 2) % 3, (it + 2) * 32);
        CP_COMMIT();

        const float* As = sm + (it % 3) * (GSTAGE_B / 4);
        const float* Bs = As + (GST_B / 4);

#pragma unroll
        for (int ks = 0; ks < 4; ks++) {
            uint32_t Ahi[4][4], Alo[4][4], Bhi[4][2], Blo[4][2];
#pragma unroll
            for (int i = 0; i < 4; i++) {
                int rb = wm * 64 + i * 16 + r;
                int cc = ks * 8 + q;
                split32(As[rb * GPAD + cc],           Ahi[i][0], Alo[i][0]);
                split32(As[(rb + 8) * GPAD + cc],     Ahi[i][1], Alo[i][1]);
                split32(As[rb * GPAD + cc + 4],       Ahi[i][2], Alo[i][2]);
                split32(As[(rb + 8) * GPAD + cc + 4], Ahi[i][3], Alo[i][3]);
            }
#pragma unroll
            for (int j = 0; j < 4; j++) {
                int nb = wn * 32 + j * 8 + r;
                int cc = ks * 8 + q;
                split32(Bs[nb * GPAD + cc],     Bhi[j][0], Blo[j][0]);
                split32(Bs[nb * GPAD + cc + 4], Bhi[j][1], Blo[j][1]);
            }
#pragma unroll
            for (int i = 0; i < 4; i++)
#pragma unroll
                for (int j = 0; j < 4; j++) {
                    mma_tf32(c[i][j], Ahi[i], Bhi[j]);
                    mma_tf32(c[i][j], Alo[i], Bhi[j]);
                    mma_tf32(c[i][j], Ahi[i], Blo[j]);
                }
        }
    }

    if (sg.mode == OM_F32) {
#pragma unroll
        for (int i = 0; i < 4; i++)
#pragma unroll
            for (int j = 0; j < 4; j++) {
                int row0 = bm + wm * 64 + i * 16 + r;
                int col  = bn + wn * 32 + j * 8 + 2 * q;
                *(float2*)&sg.cF[(size_t)row0 * sg.ldF + col] =
                    make_float2(c[i][j][0], c[i][j][1]);
                *(float2*)&sg.cF[(size_t)(row0 + 8) * sg.ldF + col] =
                    make_float2(c[i][j][2], c[i][j][3]);
            }
    } else {
        const int bnw = bn >> 1;
#pragma unroll
        for (int i = 0; i < 4; i++)
#pragma unroll
            for (int j = 0; j < 4; j++) {
                int row0 = bm + wm * 64 + i * 16 + r;
                uint32_t ww = bnw + wn * 16 + j * 4 + q;
                uint32_t ow = ww + (ww & ~31u);      // head remap (c-half)
                uint32_t hw, mw;
                split_pack(c[i][j][0], c[i][j][1], hw, mw);
                sg.cH[(size_t)row0 * sg.ldW + ow] = hw;
                sg.cM[(size_t)row0 * sg.ldW + ow] = mw;
                split_pack(c[i][j][2], c[i][j][3], hw, mw);
                sg.cH[(size_t)(row0 + 8) * sg.ldW + ow] = hw;
                sg.cM[(size_t)(row0 + 8) * sg.ldW + ow] = mw;
            }
    }
}

// ============ split_vr: V transpose+split, rope-split of kr/qr =============
__global__ __launch_bounds__(256) void split_vr(
    const float* __restrict__ vl,
    const float* __restrict__ kr, const float* __restrict__ qr,
    uint32_t* __restrict__ VTH, uint32_t* __restrict__ VTM,
    uint32_t* __restrict__ QH, uint32_t* __restrict__ QM,
    uint32_t* __restrict__ KH, uint32_t* __restrict__ KM)
{
    __shared__ float smT[128 * 66];
    const int bx = blockIdx.x, tid = threadIdx.x;
    if (bx < 1024) {
        const int pt = bx & 31, h = (bx >> 5) & 15, b = bx >> 9;
        const int t0 = pt * 64;
        for (int i = tid; i < 64 * 128; i += 256) {
            int row = i >> 7, col = i & 127;
            smT[col * 66 + row] =
                vl[(size_t)(b * TDIM + t0 + row) * 2048 + h * DH + col];
        }
        __syncthreads();
        const int lane = tid & 31, w = tid >> 5;
#pragma unroll
        for (int pass = 0; pass < 16; pass++) {
            int d = pass * 8 + w;
            float2 v = *(float2*)&smT[d * 66 + 2 * lane];
            uint32_t hw, mw; split_pack(v.x, v.y, hw, mw);
            size_t o = ((size_t)(b * HNUM + h) * 128 + d) * 1024 + pt * 32 + lane;
            VTH[o] = hw; VTM[o] = mw;
        }
    } else {
        const int rid = bx - 1024;
        const int tens = rid >> 11;
        const int baserow = (rid & 2047) * 2;
        const float* src = tens ? qr : kr;
        uint32_t* OH = tens ? QH : KH;
        uint32_t* OM = tens ? QM : KM;
#pragma unroll
        for (int j = 0; j < 4; j++) {
            int u = tid + j * 256;
            int row = baserow + (u >> 9);
            int w = u & 511;
            int h = w >> 5, u5 = w & 31;
            float2 v = *(const float2*)&src[(size_t)row * 1024 + h * HD2 + 2 * u5];
            int t = row & (TDIM - 1);
            int pr = h * 32 + u5;
            const float c1 = (float)(-9.210340371976184 / 1024.0);
            float fr  = expf((float)(2 * pr) * c1);
            float ang = (float)t * fr;
            double ad = (double)ang;
            double rr = ad - floor(ad * 0.15915494309189535) * 6.283185307179586;
            float s = sinf((float)rr), cc = cosf((float)rr);
            float xe = v.x, xo = v.y;
            float r0 = xe * cc - xo * s;
            float r1 = xo * cc + xe * s;
            uint32_t hw, mw; split_pack(r0, r1, hw, mw);
            OH[(size_t)row * 1024 + h * 64 + 32 + u5] = hw;
            OM[(size_t)row * 1024 + h * 64 + 32 + u5] = mw;
        }
    }
}

// ====================== bf16x3 flash attention (fp32 out) ==================
#define AQH 0
#define AQM 4352
#define AKH 8704
#define AKM 13056
#define AVH 17408
#define AVM 19968
#define APH 22528
#define APM 23808
#define ATTN_SMEM (25088 * 4)

__global__ __launch_bounds__(128) void attn_bf3(
    const uint32_t* __restrict__ QHg, const uint32_t* __restrict__ QMg,
    const uint32_t* __restrict__ KHg, const uint32_t* __restrict__ KMg,
    const uint32_t* __restrict__ VTHg, const uint32_t* __restrict__ VTMg,
    float* __restrict__ Og)
{
    extern __shared__ uint32_t smw[];
    const uint32_t smb = smem_u32(smw);
    const int tid = threadIdx.x, wid = tid >> 5, lane = tid & 31;
    const int g = lane >> 2, q = lane & 3;
    const int r8 = lane & 7, mq = lane >> 3;
    const int it = 31 - blockIdx.x;
    const int h = blockIdx.y, b = blockIdx.z;
    const int q0 = it * 64, rowbase = b * TDIM;
    const float scale = 0.08838834764831845f;

    uint32_t* PH = smw + APH;  uint32_t* PM = smw + APM;

    auto cpK = [&](int tk, int slot) {
#pragma unroll
        for (int j = 0; j < 8; j++) {
            int f = tid + j * 128;
            int ff = f & 511;
            int row = ff >> 4, c4 = ff & 15;
            const uint32_t* gsrc = (f < 512) ? KHg : KMg;
            uint32_t dst = smb + (((f < 512) ? AKH : AKM) + slot * 2176
                                  + row * 68 + c4 * 4) * 4;
            cp16(dst, gsrc + (size_t)(rowbase + tk + row) * 1024 + h * 64 + c4 * 4);
        }
    };
    auto cpV = [&](int tk) {
#pragma unroll
        for (int j = 0; j < 8; j++) {
            int f = tid + j * 128;
            int ff = f & 511;
            int d = ff >> 2, c4 = ff & 3;
            const uint32_t* gsrc = (f < 512) ? VTHg : VTMg;
            uint32_t dst = smb + (((f < 512) ? AVH : AVM) + d * 20 + c4 * 4) * 4;
            cp16(dst, gsrc + ((size_t)(b * HNUM + h) * 128 + d) * 1024
                        + (tk >> 1) + c4 * 4);
        }
    };

#pragma unroll
    for (int j = 0; j < 16; j++) {
        int f = tid + j * 128;
        int ff = f & 1023;
        int row = ff >> 4, c4 = ff & 15;
        const uint32_t* gsrc = (f < 1024) ? QHg : QMg;
        uint32_t dst = smb + (((f < 1024) ? AQH : AQM) + row * 68 + c4 * 4) * 4;
        cp16(dst, gsrc + (size_t)(rowbase + q0 + row) * 1024 + h * 64 + c4 * 4);
    }
    cpK(0, 0);
    CP_COMMIT();
    cpV(0);
    CP_COMMIT();

    float o[16][4];
#pragma unroll
    for (int jt = 0; jt < 16; jt++)
#pragma unroll
        for (int e = 0; e < 4; e++) o[jt][e] = 0.f;
    float m_old0 = -1e30f, m_old1 = -1e30f, l0 = 0.f, l1 = 0.f;

    const int kmax = 2 * it + 1;
    const int gr0 = q0 + 16 * wid + g, gr1 = gr0 + 8;
    const int qwr = 16 * wid;

    for (int kb = 0; kb <= kmax; kb++) {
        if (kb < kmax) cpK((kb + 1) * 32, (kb + 1) & 1);
        CP_COMMIT();
        CP_WAIT(2);
        __syncthreads();

        const bool active = (kb * 32 <= q0 + qwr + 15);
        if (active) {
            const uint32_t sKH = smb + (uint32_t)(AKH + (kb & 1) * 2176) * 4;
            const uint32_t sKM = smb + (uint32_t)(AKM + (kb & 1) * 2176) * 4;
            const uint32_t sQH = smb + AQH * 4;
            const uint32_t sQM = smb + AQM * 4;

            float sacc[4][4];
#pragma unroll
            for (int j = 0; j < 4; j++)
#pragma unroll
                for (int e = 0; e < 4; e++) sacc[j][e] = 0.f;

#pragma unroll
            for (int c = 0; c < 8; c++) {
                uint32_t Ah[4], Am[4];
                uint32_t aoff = (uint32_t)(((qwr + r8 + (mq & 1) * 8) * 68
                                            + c * 8 + (mq >> 1) * 4) * 4);
                ldsm_x4(Ah[0], Ah[1], Ah[2], Ah[3], sQH + aoff);
                ldsm_x4(Am[0], Am[1], Am[2], Am[3], sQM + aoff);
                uint32_t Bh[4][2], Bm[4][2];
#pragma unroll
                for (int u = 0; u < 2; u++) {
                    uint32_t boff = (uint32_t)((((2 * u + (mq >> 1)) * 8 + r8) * 68
                                                + c * 8 + (mq & 1) * 4) * 4);
                    ldsm_x4(Bh[2*u][0], Bh[2*u][1], Bh[2*u+1][0], Bh[2*u+1][1], sKH + boff);
                    ldsm_x4(Bm[2*u][0], Bm[2*u][1], Bm[2*u+1][0], Bm[2*u+1][1], sKM + boff);
                }
#pragma unroll
                for (int j = 0; j < 4; j++) {
                    mma_bf16(sacc[j], Ah, Bh[j]);
                    mma_bf16(sacc[j], Ah, Bm[j]);
                    mma_bf16(sacc[j], Am, Bh[j]);
                }
            }

            float mx0 = -1e30f, mx1 = -1e30f;
#pragma unroll
            for (int j = 0; j < 4; j++) {
                int colb = kb * 32 + j * 8 + 2 * q;
                float v0 = sacc[j][0] * scale; if (colb     > gr0) v0 = -1e30f;
                float v1 = sacc[j][1] * scale; if (colb + 1 > gr0) v1 = -1e30f;
                float v2 = sacc[j][2] * scale; if (colb     > gr1) v2 = -1e30f;
                float v3 = sacc[j][3] * scale; if (colb + 1 > gr1) v3 = -1e30f;
                sacc[j][0] = v0; sacc[j][1] = v1; sacc[j][2] = v2; sacc[j][3] = v3;
                mx0 = fmaxf(mx0, fmaxf(v0, v1));
                mx1 = fmaxf(mx1, fmaxf(v2, v3));
            }
            mx0 = fmaxf(mx0, __shfl_xor_sync(0xffffffffu, mx0, 1));
            mx0 = fmaxf(mx0, __shfl_xor_sync(0xffffffffu, mx0, 2));
            mx1 = fmaxf(mx1, __shfl_xor_sync(0xffffffffu, mx1, 1));
            mx1 = fmaxf(mx1, __shfl_xor_sync(0xffffffffu, mx1, 2));

            float mn0 = fmaxf(m_old0, mx0), mn1 = fmaxf(m_old1, mx1);
            float al0 = fexp(m_old0 - mn0), al1 = fexp(m_old1 - mn1);
            float ps0 = 0.f, ps1 = 0.f;
#pragma unroll
            for (int j = 0; j < 4; j++) {
                float p0 = fexp(sacc[j][0] - mn0);
                float p1 = fexp(sacc[j][1] - mn0);
                float p2 = fexp(sacc[j][2] - mn1);
                float p3 = fexp(sacc[j][3] - mn1);
                ps0 += p0 + p1; ps1 += p2 + p3;
                uint32_t hw, mw;
                split_pack(p0, p1, hw, mw);
                PH[(qwr + g) * 20 + j * 4 + q] = hw;
                PM[(qwr + g) * 20 + j * 4 + q] = mw;
                split_pack(p2, p3, hw, mw);
                PH[(qwr + g + 8) * 20 + j * 4 + q] = hw;
                PM[(qwr + g + 8) * 20 + j * 4 + q] = mw;
            }
            ps0 += __shfl_xor_sync(0xffffffffu, ps0, 1);
            ps0 += __shfl_xor_sync(0xffffffffu, ps0, 2);
            ps1 += __shfl_xor_sync(0xffffffffu, ps1, 1);
            ps1 += __shfl_xor_sync(0xffffffffu, ps1, 2);
            l0 = l0 * al0 + ps0; l1 = l1 * al1 + ps1;
            m_old0 = mn0; m_old1 = mn1;
#pragma unroll
            for (int jt = 0; jt < 16; jt++) {
                o[jt][0] *= al0; o[jt][1] *= al0;
                o[jt][2] *= al1; o[jt][3] *= al1;
            }
        }

        CP_WAIT(1);
        __syncthreads();

        if (active) {
            __syncwarp();
            const uint32_t sPH = smb + APH * 4;
            const uint32_t sPM = smb + APM * 4;
            const uint32_t sVH = smb + AVH * 4;
            const uint32_t sVM = smb + AVM * 4;
#pragma unroll
            for (int c = 0; c < 2; c++) {
                uint32_t Ah[4], Am[4];
                uint32_t aoff = (uint32_t)(((qwr + r8 + (mq & 1) * 8) * 20
                                            + c * 8 + (mq >> 1) * 4) * 4);
                ldsm_x4(Ah[0], Ah[1], Ah[2], Ah[3], sPH + aoff);
                ldsm_x4(Am[0], Am[1], Am[2], Am[3], sPM + aoff);
#pragma unroll
                for (int u = 0; u < 8; u++) {
                    uint32_t Bh[2][2], Bm[2][2];
                    uint32_t boff = (uint32_t)((((2 * u + (mq >> 1)) * 8 + r8) * 20
                                                + c * 8 + (mq & 1) * 4) * 4);
                    ldsm_x4(Bh[0][0], Bh[0][1], Bh[1][0], Bh[1][1], sVH + boff);
                    ldsm_x4(Bm[0][0], Bm[0][1], Bm[1][0], Bm[1][1], sVM + boff);
#pragma unroll
                    for (int t2 = 0; t2 < 2; t2++) {
                        int jt = 2 * u + t2;
                        mma_bf16(o[jt], Ah, Bh[t2]);
                        mma_bf16(o[jt], Ah, Bm[t2]);
                        mma_bf16(o[jt], Am, Bh[t2]);
                    }
                }
            }
        }

        __syncthreads();
        if (kb < kmax) cpV((kb + 1) * 32);
        CP_COMMIT();
    }

    // epilogue: fp32 attn (feeds tf32 Wo gemm)
    float inv0 = 1.f / l0, inv1 = 1.f / l1;
    size_t ob0 = (size_t)(rowbase + gr0) * CDIM + h * DH;
    size_t ob1 = (size_t)(rowbase + gr1) * CDIM + h * DH;
#pragma unroll
    for (int jt = 0; jt < 16; jt++) {
        *(float2*)&Og[ob0 + jt * 8 + 2 * q] =
            make_float2(o[jt][0] * inv0, o[jt][1] * inv0);
        *(float2*)&Og[ob1 + jt * 8 + 2 * q] =
            make_float2(o[jt][2] * inv1, o[jt][3] * inv1);
    }
}

// ------------------------------- launch ------------------------------------
extern "C" void kernel_launch(void* const* d_in, const int* in_sizes, int n_in,
                              void* d_out, int out_size)
{
    (void)in_sizes; (void)n_in; (void)out_size;
    const float* x    = (const float*)d_in[0];
    const float* WkvD = (const float*)d_in[1];
    const float* WqD  = (const float*)d_in[2];
    const float* WkU  = (const float*)d_in[3];
    const float* WvU  = (const float*)d_in[4];
    const float* WqU  = (const float*)d_in[5];
    const float* Wrk  = (const float*)d_in[6];
    const float* Wrq  = (const float*)d_in[7];
    const float* Wo   = (const float*)d_in[8];
    float* out = (float*)d_out;

    float *kvd, *qd, *vl, *kr, *qr, *attn;
    uint32_t *QH, *QM, *KH, *KM, *VTH, *VTM;
    cudaGetSymbolAddress((void**)&kvd,  g_kvd);
    cudaGetSymbolAddress((void**)&qd,   g_qd);
    cudaGetSymbolAddress((void**)&vl,   g_vl);
    cudaGetSymbolAddress((void**)&kr,   g_kr);
    cudaGetSymbolAddress((void**)&qr,   g_qr);
    cudaGetSymbolAddress((void**)&attn, g_attn);
    cudaGetSymbolAddress((void**)&QH,   g_QH);   cudaGetSymbolAddress((void**)&QM,  g_QM);
    cudaGetSymbolAddress((void**)&KH,   g_KH);   cudaGetSymbolAddress((void**)&KM,  g_KM);
    cudaGetSymbolAddress((void**)&VTH,  g_VTH);  cudaGetSymbolAddress((void**)&VTM, g_VTM);

    cudaFuncSetAttribute(gemm_tf32, cudaFuncAttributeMaxDynamicSharedMemorySize,
                         GEMM_SMEM);
    cudaFuncSetAttribute(attn_bf3, cudaFuncAttributeMaxDynamicSharedMemorySize,
                         ATTN_SMEM);

    // L1: x -> {kvd, qd, kr}   K=2048
    {
        GBatch gb;
        gb.s[0] = { x, WkvD, kvd, nullptr, nullptr, 512,  0, OM_F32, 4 };
        gb.s[1] = { x, WqD,  qd,  nullptr, nullptr, 512,  0, OM_F32, 8 };
        gb.s[2] = { x, Wrk,  kr,  nullptr, nullptr, 1024, 0, OM_F32, 16 };
        gb.s[3] = gb.s[2];
        gemm_tf32<<<dim3(16, 32), 256, GEMM_SMEM>>>(gb, 2048);
    }
    // L2: {kvd,qd} -> {kc->K(split), qc->Q(split), vl, qr}   K=512
    {
        GBatch gb;
        gb.s[0] = { kvd, WkU, nullptr, KH, KM, 0, 1024, OM_QKMAP, 8 };
        gb.s[1] = { qd,  WqU, nullptr, QH, QM, 0, 1024, OM_QKMAP, 16 };
        gb.s[2] = { kvd, WvU, vl, nullptr, nullptr, 2048, 0, OM_F32, 32 };
        gb.s[3] = { qd,  Wrq, qr, nullptr, nullptr, 1024, 0, OM_F32, 40 };
        gemm_tf32<<<dim3(40, 32), 256, GEMM_SMEM>>>(gb, 512);
    }
    // L3: V transpose+split, rope+split of kr/qr
    split_vr<<<5120, 256>>>(vl, kr, qr, VTH, VTM, QH, QM, KH, KM);
    // L4 (ncu-captured): attention (bf16x3), fp32 output
    attn_bf3<<<dim3(32, HNUM, 2), 128, ATTN_SMEM>>>(
        QH, QM, KH, KM, VTH, VTM, attn);
    // L5: output projection   K=2048
    {
        GBatch gb;
        gb.s[0] = { attn, Wo, out, nullptr, nullptr, 2048, 0, OM_F32, 16 };
        gb.s[1] = gb.s[0]; gb.s[2] = gb.s[0]; gb.s[3] = gb.s[0];
        gemm_tf32<<<dim3(16, 32), 256, GEMM_SMEM>>>(gb, 2048);
    }
}